// round 10
// baseline (speedup 1.0000x reference)
#include <cuda_runtime.h>
#include <cuda_fp16.h>
#include <cstdint>

// ---------------------------------------------------------------------------
// Mipmapped texture sampling, fp16 pyramid + spatially binned queries.
//   K1 k_zero:      clear bin counters (graph-replay safe).
//   K2 k_transpose: (C,H,W) f32 -> (H,W,C) f16 level 0.
//   K3 k_mips:      levels 1..7 from level 0.
//   K4 k_scatter:   bin queries by uv into a 64x64 grid; packed (u,v,p,q).
//   K5 k_sample:    one bin per block; warps see spatially coherent taps
//                   (shared cache lines + L1-resident mid levels).
// ---------------------------------------------------------------------------

#define NUM_LEVELS 8
#define BASE_W     512
#define CHANNELS   16

#define TOTAL_PIX  349520
#define L0_PIX     (512*512)
#define MIP_PIX    (TOTAL_PIX - L0_PIX)

#define BGRID      64                 // bins per axis
#define NBINS      (BGRID*BGRID)      // 4096
#define CAP        512                // record capacity per bin (mean ~244)

__device__ __half g_pyr[(size_t)TOTAL_PIX * CHANNELS];   // ~11.2 MB
__device__ int    g_cnt[NBINS];
__device__ float4 g_rec[(size_t)NBINS * CAP];            // 33.5 MB

__device__ __forceinline__ int lvl_off(int l) {
    return (1048576 - (1048576 >> (2 * l))) / 3;
}

// ------------------------- Kernel 0: zero counters -------------------------
__global__ void k_zero() {
    int i = blockIdx.x * blockDim.x + threadIdx.x;
    if (i < NBINS) g_cnt[i] = 0;
}

// ------------------------- Kernel 1: transpose + quantize ------------------
__global__ void k_transpose(const float* __restrict__ tex) {
    int pix = blockIdx.x * blockDim.x + threadIdx.x;   // 0..262143
    float v[CHANNELS];
#pragma unroll
    for (int c = 0; c < CHANNELS; ++c)
        v[c] = __ldg(&tex[(size_t)c * L0_PIX + pix]);
    __half2 h[8];
#pragma unroll
    for (int i = 0; i < 8; ++i)
        h[i] = __floats2half2_rn(v[2*i], v[2*i+1]);
    uint4* dst = reinterpret_cast<uint4*>(g_pyr + (size_t)pix * CHANNELS);
    dst[0] = *reinterpret_cast<uint4*>(&h[0]);
    dst[1] = *reinterpret_cast<uint4*>(&h[4]);
}

// ------------------------- Kernel 2: build mips ----------------------------
__device__ __forceinline__ void load_texel16(const __half* ptr, float* f) {
    const uint4* p4 = reinterpret_cast<const uint4*>(ptr);
    uint4 a = p4[0], b = p4[1];
    const __half2* ha = reinterpret_cast<const __half2*>(&a);
    const __half2* hb = reinterpret_cast<const __half2*>(&b);
#pragma unroll
    for (int i = 0; i < 4; ++i) {
        float2 t = __half22float2(ha[i]);
        f[2*i] = t.x; f[2*i+1] = t.y;
    }
#pragma unroll
    for (int i = 0; i < 4; ++i) {
        float2 t = __half22float2(hb[i]);
        f[8+2*i] = t.x; f[8+2*i+1] = t.y;
    }
}

__global__ void k_mips() {
    int idx = blockIdx.x * blockDim.x + threadIdx.x;
    if (idx >= MIP_PIX) return;

    int l = 1, rem = idx;
#pragma unroll
    for (int i = 1; i < NUM_LEVELS; ++i) {
        int n = (BASE_W >> i) * (BASE_W >> i);
        if (rem < n) { l = i; break; }
        rem -= n;
    }
    int w = BASE_W >> l;
    int y = rem / w;
    int x = rem - y * w;
    float s = (float)(1 << l);

    float sy = fmaxf((y + 0.5f) * s - 0.5f, 0.0f);
    float sx = fmaxf((x + 0.5f) * s - 0.5f, 0.0f);
    int y0 = min((int)sy, BASE_W - 1);
    int x0 = min((int)sx, BASE_W - 1);
    int y1 = min(y0 + 1, BASE_W - 1);
    int x1 = min(x0 + 1, BASE_W - 1);
    float ty = sy - (float)y0;
    float tx = sx - (float)x0;

    float w00 = (1.0f - tx) * (1.0f - ty);
    float w01 = tx * (1.0f - ty);
    float w10 = (1.0f - tx) * ty;
    float w11 = tx * ty;

    float a[16], b[16], c[16], d[16];
    load_texel16(g_pyr + (size_t)(y0 * BASE_W + x0) * CHANNELS, a);
    load_texel16(g_pyr + (size_t)(y0 * BASE_W + x1) * CHANNELS, b);
    load_texel16(g_pyr + (size_t)(y1 * BASE_W + x0) * CHANNELS, c);
    load_texel16(g_pyr + (size_t)(y1 * BASE_W + x1) * CHANNELS, d);

    __half2 h[8];
#pragma unroll
    for (int i = 0; i < 8; ++i) {
        float r0 = a[2*i]   * w00 + b[2*i]   * w01 + c[2*i]   * w10 + d[2*i]   * w11;
        float r1 = a[2*i+1] * w00 + b[2*i+1] * w01 + c[2*i+1] * w10 + d[2*i+1] * w11;
        h[i] = __floats2half2_rn(r0, r1);
    }
    uint4* dst = reinterpret_cast<uint4*>(g_pyr + (size_t)(lvl_off(l) + rem) * CHANNELS);
    dst[0] = *reinterpret_cast<uint4*>(&h[0]);
    dst[1] = *reinterpret_cast<uint4*>(&h[4]);
}

// ------------------------- Kernel 3: scatter into bins ---------------------
__global__ void k_scatter(const float2* __restrict__ uv,
                          const float* __restrict__ p, int n) {
    int q = blockIdx.x * blockDim.x + threadIdx.x;
    if (q >= n) return;
    float2 u = __ldg(&uv[q]);
    float pq = __ldg(&p[q]);
    int bx = min(max((int)(u.x * (float)BGRID), 0), BGRID - 1);
    int by = min(max((int)(u.y * (float)BGRID), 0), BGRID - 1);
    int bin = by * BGRID + bx;
    int slot = atomicAdd(&g_cnt[bin], 1);
    if (slot < CAP)
        g_rec[(size_t)bin * CAP + slot] =
            make_float4(u.x, u.y, pq, __int_as_float(q));
}

// ------------------------- Kernel 4: sample --------------------------------
// One bin per block. 4 lanes/query: lane bit0 = xsel, bit1 = channel half.
__global__ void __launch_bounds__(1024)
k_sample(float* __restrict__ out) {
    int bin = blockIdx.x;
    int cnt = min(g_cnt[bin], CAP);
    if (cnt == 0) return;
    const float4* recs = g_rec + (size_t)bin * CAP;

    int lane = threadIdx.x & 3;
    int xsel = lane & 1;
    int cg   = lane >> 1;

    for (int i0 = 0; i0 < cnt; i0 += 256) {
        int i = i0 + (int)(threadIdx.x >> 2);
        bool valid = (i < cnt);
        float4 rec = recs[valid ? i : (cnt - 1)];
        float2 uvq = make_float2(rec.x, rec.y);
        int q = __float_as_int(rec.w);

        float lf = rec.z * (float)(NUM_LEVELS - 1);
        int l0 = min((int)lf, NUM_LEVELS - 1);
        int l1 = min(l0 + 1, NUM_LEVELS - 1);
        float alpha = lf - (float)l0;

        const uint4* pA[2];
        const uint4* pB[2];
        float wx[2], fyv[2];
#pragma unroll
        for (int k = 0; k < 2; ++k) {
            int l = k ? l1 : l0;
            int w = BASE_W >> l;
            float fw = (float)(w - 1);
            float x = fminf(fmaxf(uvq.x * fw, 0.0f), fw);
            float y = fminf(fmaxf(uvq.y * fw, 0.0f), fw);
            int x0 = (int)x;
            int y0 = (int)y;
            int x1 = min(x0 + 1, w - 1);
            int y1 = min(y0 + 1, w - 1);
            float fx = x - (float)x0;
            int xs = xsel ? x1 : x0;
            const uint4* base = reinterpret_cast<const uint4*>(
                g_pyr + (size_t)lvl_off(l) * CHANNELS) + cg;
            pA[k] = base + (size_t)(y0 * w + xs) * 2;
            pB[k] = base + (size_t)(y1 * w + xs) * 2;
            wx[k]  = xsel ? fx : 1.0f - fx;
            fyv[k] = y - (float)y0;
        }

        uint4 a0 = __ldg(pA[0]);
        uint4 b0 = __ldg(pB[0]);
        uint4 a1 = __ldg(pA[1]);
        uint4 b1 = __ldg(pB[1]);

        float w0 = (1.0f - alpha) * wx[0];
        float w1 = alpha * wx[1];
        float fy0 = fyv[0], fy1 = fyv[1];

        const __half2* hA0 = reinterpret_cast<const __half2*>(&a0);
        const __half2* hB0 = reinterpret_cast<const __half2*>(&b0);
        const __half2* hA1 = reinterpret_cast<const __half2*>(&a1);
        const __half2* hB1 = reinterpret_cast<const __half2*>(&b1);

        float s[8];
#pragma unroll
        for (int j = 0; j < 4; ++j) {
            float2 fa0 = __half22float2(hA0[j]);
            float2 fb0 = __half22float2(hB0[j]);
            float2 fa1 = __half22float2(hA1[j]);
            float2 fb1 = __half22float2(hB1[j]);
            float v0x = fa0.x + fy0 * (fb0.x - fa0.x);
            float v0y = fa0.y + fy0 * (fb0.y - fa0.y);
            float v1x = fa1.x + fy1 * (fb1.x - fa1.x);
            float v1y = fa1.y + fy1 * (fb1.y - fa1.y);
            s[2*j]   = v0x * w0 + v1x * w1;
            s[2*j+1] = v0y * w0 + v1y * w1;
        }

        // sum the two x taps (partner lane differs in bit 0)
#pragma unroll
        for (int j = 0; j < 8; ++j)
            s[j] += __shfl_xor_sync(0xFFFFFFFFu, s[j], 1);

        if (valid) {
            float4 o = xsel ? make_float4(s[4], s[5], s[6], s[7])
                            : make_float4(s[0], s[1], s[2], s[3]);
            reinterpret_cast<float4*>(out + (size_t)q * CHANNELS)[lane] = o;
        }
    }
}

// ---------------------------------------------------------------------------
extern "C" void kernel_launch(void* const* d_in, const int* in_sizes, int n_in,
                              void* d_out, int out_size) {
    const float* uv  = (const float*)d_in[0];
    const float* p   = (const float*)d_in[1];
    const float* tex = (const float*)d_in[2];
    float* out = (float*)d_out;
    int n = in_sizes[1];

    k_zero<<<(NBINS + 255) / 256, 256>>>();
    k_transpose<<<L0_PIX / 256, 256>>>(tex);
    k_mips<<<(MIP_PIX + 255) / 256, 256>>>();
    k_scatter<<<(n + 255) / 256, 256>>>((const float2*)uv, p, n);
    k_sample<<<NBINS, 1024>>>(out);
}

// round 12
// speedup vs baseline: 2.6079x; 2.6079x over previous
#include <cuda_runtime.h>
#include <cuda_fp16.h>
#include <cstdint>

// ---------------------------------------------------------------------------
// Mipmapped texture sampling, fp16 pyramid (round-9 sampler = LTS-cap bound).
//   K1: transpose (C,H,W) f32 -> (H,W,C) f16; 2 threads/pixel (8 ch each)
//       for 2x warp-level parallelism on the latency-bound first wave.
//   K2: levels 1..7 from level 0.
//   K3: 4 lanes/query sampler (proven 35 us, at LTS cap).
// ---------------------------------------------------------------------------

#define NUM_LEVELS 8
#define BASE_W     512
#define CHANNELS   16

#define TOTAL_PIX  349520
#define L0_PIX     (512*512)
#define MIP_PIX    (TOTAL_PIX - L0_PIX)

__device__ __half g_pyr[(size_t)TOTAL_PIX * CHANNELS];   // ~11.2 MB

__device__ __forceinline__ int lvl_off(int l) {
    return (1048576 - (1048576 >> (2 * l))) / 3;
}

// ------------------------- Kernel 1: transpose + quantize ------------------
// 2 threads per pixel; thread handles 8 channels -> one 16 B store.
__global__ void k_transpose(const float* __restrict__ tex) {
    int tid = blockIdx.x * blockDim.x + threadIdx.x;   // 0..524287
    int pix  = tid >> 1;
    int half = tid & 1;                                // channel half

    const float* src = tex + (size_t)(half * 8) * L0_PIX + pix;
    float v[8];
#pragma unroll
    for (int c = 0; c < 8; ++c)
        v[c] = __ldg(&src[(size_t)c * L0_PIX]);

    __half2 h[4];
#pragma unroll
    for (int i = 0; i < 4; ++i)
        h[i] = __floats2half2_rn(v[2*i], v[2*i+1]);

    reinterpret_cast<uint4*>(g_pyr)[pix * 2 + half] =
        *reinterpret_cast<uint4*>(&h[0]);
}

// ------------------------- Kernel 2: build mips ----------------------------
__device__ __forceinline__ void load_texel16(const __half* ptr, float* f) {
    const uint4* p4 = reinterpret_cast<const uint4*>(ptr);
    uint4 a = p4[0], b = p4[1];
    const __half2* ha = reinterpret_cast<const __half2*>(&a);
    const __half2* hb = reinterpret_cast<const __half2*>(&b);
#pragma unroll
    for (int i = 0; i < 4; ++i) {
        float2 t = __half22float2(ha[i]);
        f[2*i] = t.x; f[2*i+1] = t.y;
    }
#pragma unroll
    for (int i = 0; i < 4; ++i) {
        float2 t = __half22float2(hb[i]);
        f[8+2*i] = t.x; f[8+2*i+1] = t.y;
    }
}

__global__ void k_mips() {
    int idx = blockIdx.x * blockDim.x + threadIdx.x;
    if (idx >= MIP_PIX) return;

    int l = 1, rem = idx;
#pragma unroll
    for (int i = 1; i < NUM_LEVELS; ++i) {
        int n = (BASE_W >> i) * (BASE_W >> i);
        if (rem < n) { l = i; break; }
        rem -= n;
    }
    int w = BASE_W >> l;
    int y = rem / w;
    int x = rem - y * w;
    float s = (float)(1 << l);

    float sy = fmaxf((y + 0.5f) * s - 0.5f, 0.0f);
    float sx = fmaxf((x + 0.5f) * s - 0.5f, 0.0f);
    int y0 = min((int)sy, BASE_W - 1);
    int x0 = min((int)sx, BASE_W - 1);
    int y1 = min(y0 + 1, BASE_W - 1);
    int x1 = min(x0 + 1, BASE_W - 1);
    float ty = sy - (float)y0;
    float tx = sx - (float)x0;

    float w00 = (1.0f - tx) * (1.0f - ty);
    float w01 = tx * (1.0f - ty);
    float w10 = (1.0f - tx) * ty;
    float w11 = tx * ty;

    float a[16], b[16], c[16], d[16];
    load_texel16(g_pyr + (size_t)(y0 * BASE_W + x0) * CHANNELS, a);
    load_texel16(g_pyr + (size_t)(y0 * BASE_W + x1) * CHANNELS, b);
    load_texel16(g_pyr + (size_t)(y1 * BASE_W + x0) * CHANNELS, c);
    load_texel16(g_pyr + (size_t)(y1 * BASE_W + x1) * CHANNELS, d);

    __half2 h[8];
#pragma unroll
    for (int i = 0; i < 8; ++i) {
        float r0 = a[2*i]   * w00 + b[2*i]   * w01 + c[2*i]   * w10 + d[2*i]   * w11;
        float r1 = a[2*i+1] * w00 + b[2*i+1] * w01 + c[2*i+1] * w10 + d[2*i+1] * w11;
        h[i] = __floats2half2_rn(r0, r1);
    }
    uint4* dst = reinterpret_cast<uint4*>(g_pyr + (size_t)(lvl_off(l) + rem) * CHANNELS);
    dst[0] = *reinterpret_cast<uint4*>(&h[0]);
    dst[1] = *reinterpret_cast<uint4*>(&h[4]);
}

// ------------------------- Kernel 3: sample --------------------------------
// 4 lanes per query. lane bit0 = xsel (x0/x1 tap), bit1 = cg (channel half).
__global__ void __launch_bounds__(256)
k_sample(const float2* __restrict__ uv,
         const float* __restrict__ p,
         float* __restrict__ out, int n) {
    int tid = blockIdx.x * blockDim.x + threadIdx.x;
    int q = tid >> 2;
    bool valid = (q < n);
    int qc = valid ? q : (n - 1);          // clamp; keep full warp for shfl
    int lane = tid & 3;
    int xsel = lane & 1;
    int cg   = lane >> 1;

    float2 uvq = __ldg(&uv[qc]);
    float lf = __ldg(&p[qc]) * (float)(NUM_LEVELS - 1);
    int l0 = min((int)lf, NUM_LEVELS - 1);
    int l1 = min(l0 + 1, NUM_LEVELS - 1);
    float alpha = lf - (float)l0;

    const uint4* pA[2];
    const uint4* pB[2];
    float wx[2], fyv[2];
#pragma unroll
    for (int k = 0; k < 2; ++k) {
        int l = k ? l1 : l0;
        int w = BASE_W >> l;
        float fw = (float)(w - 1);
        float x = fminf(fmaxf(uvq.x * fw, 0.0f), fw);
        float y = fminf(fmaxf(uvq.y * fw, 0.0f), fw);
        int x0 = (int)x;
        int y0 = (int)y;
        int x1 = min(x0 + 1, w - 1);
        int y1 = min(y0 + 1, w - 1);
        float fx = x - (float)x0;
        int xs = xsel ? x1 : x0;
        const uint4* base = reinterpret_cast<const uint4*>(
            g_pyr + (size_t)lvl_off(l) * CHANNELS) + cg;
        pA[k] = base + (size_t)(y0 * w + xs) * 2;   // row y0
        pB[k] = base + (size_t)(y1 * w + xs) * 2;   // row y1
        wx[k]  = xsel ? fx : 1.0f - fx;
        fyv[k] = y - (float)y0;
    }

    uint4 a0 = __ldg(pA[0]);
    uint4 b0 = __ldg(pB[0]);
    uint4 a1 = __ldg(pA[1]);
    uint4 b1 = __ldg(pB[1]);

    float w0 = (1.0f - alpha) * wx[0];
    float w1 = alpha * wx[1];
    float fy0 = fyv[0], fy1 = fyv[1];

    const __half2* hA0 = reinterpret_cast<const __half2*>(&a0);
    const __half2* hB0 = reinterpret_cast<const __half2*>(&b0);
    const __half2* hA1 = reinterpret_cast<const __half2*>(&a1);
    const __half2* hB1 = reinterpret_cast<const __half2*>(&b1);

    float s[8];
#pragma unroll
    for (int i = 0; i < 4; ++i) {
        float2 fa0 = __half22float2(hA0[i]);
        float2 fb0 = __half22float2(hB0[i]);
        float2 fa1 = __half22float2(hA1[i]);
        float2 fb1 = __half22float2(hB1[i]);
        float v0x = fa0.x + fy0 * (fb0.x - fa0.x);
        float v0y = fa0.y + fy0 * (fb0.y - fa0.y);
        float v1x = fa1.x + fy1 * (fb1.x - fa1.x);
        float v1y = fa1.y + fy1 * (fb1.y - fa1.y);
        s[2*i]   = v0x * w0 + v1x * w1;
        s[2*i+1] = v0y * w0 + v1y * w1;
    }

#pragma unroll
    for (int i = 0; i < 8; ++i)
        s[i] += __shfl_xor_sync(0xFFFFFFFFu, s[i], 1);

    if (valid) {
        float4 o = xsel ? make_float4(s[4], s[5], s[6], s[7])
                        : make_float4(s[0], s[1], s[2], s[3]);
        reinterpret_cast<float4*>(out + (size_t)q * CHANNELS)[lane] = o;
    }
}

// ---------------------------------------------------------------------------
extern "C" void kernel_launch(void* const* d_in, const int* in_sizes, int n_in,
                              void* d_out, int out_size) {
    const float* uv  = (const float*)d_in[0];
    const float* p   = (const float*)d_in[1];
    const float* tex = (const float*)d_in[2];
    float* out = (float*)d_out;
    int n = in_sizes[1];

    k_transpose<<<L0_PIX * 2 / 256, 256>>>(tex);
    k_mips<<<(MIP_PIX + 255) / 256, 256>>>();

    int threads = n * 4;
    k_sample<<<(threads + 255) / 256, 256>>>(
        (const float2*)uv, p, out, n);
}